// round 17
// baseline (speedup 1.0000x reference)
#include <cuda_runtime.h>
#include <cuda_bf16.h>
#include <math.h>
#include <stdint.h>

#define Bn   8
#define Ln   9216
#define Cn   512
#define Hn   8
#define DK   64
#define HID  2048
#define Mrows (Bn*Ln)          // 73728
#define QKV  1536              // fused q|k|v width
#define CTXN (Bn*Hn*DK*DK)     // 262144 floats

// ---------------- scratch (device globals: no runtime allocation) ----------
__device__ float          g_xnT [Mrows*Cn];   // fp32 xn transposed (B,C,L)
__device__ __nv_bfloat16  g_xnb [Mrows*Cn];   // bf16 xn (GEMM A)
__device__ __nv_bfloat16  g_vnb [Mrows*Cn];   // bf16 vn (GEMM A)
__device__ __nv_bfloat16  g_qkvb[Mrows*QKV];  // bf16 fused [q | k | v]
__device__ float          g_ksum[Bn*Cn];      // per-(b,ck) sum of exp(k) over L
__device__ float          g_ctx [CTXN];       // UNNORMALIZED context
__device__ __nv_bfloat16  g_aggT[Mrows*Cn];   // (B, L, C) bf16 (reproj B operand)
__device__ float          g_x1  [Mrows*Cn];   // x1 = reproj + br + xn^T + x (flat)
__device__ __nv_bfloat16  g_x1nb[Mrows*Cn];   // bf16 LN2 out (fc1 A)
__device__ __nv_bfloat16  g_h1b [Mrows*HID];  // bf16 gelu(fc1) (fc2 A)
// bf16 weights
__device__ __nv_bfloat16  g_wqkvb[QKV*Cn];    // [wq ; wk ; wv]
__device__ __nv_bfloat16  g_wrb  [Cn*Cn];
__device__ __nv_bfloat16  g_f1b  [HID*Cn];
__device__ __nv_bfloat16  g_f2b  [Cn*HID];
__device__ float          g_bqkv [QKV];       // [bq ; bk ; bv]

// ---------------- asm helpers ------------------------------------------------
__device__ __forceinline__ uint32_t smem_u32(const void* p) {
    uint32_t a;
    asm("{ .reg .u64 t; cvta.to.shared.u64 t, %1; cvt.u32.u64 %0, t; }" : "=r"(a) : "l"(p));
    return a;
}
__device__ __forceinline__ void ldsm4(uint32_t* r, uint32_t a) {
    asm volatile("ldmatrix.sync.aligned.m8n8.x4.shared.b16 {%0,%1,%2,%3}, [%4];"
        : "=r"(r[0]), "=r"(r[1]), "=r"(r[2]), "=r"(r[3]) : "r"(a));
}
__device__ __forceinline__ void ldsm4t(uint32_t* r, uint32_t a) {
    asm volatile("ldmatrix.sync.aligned.m8n8.x4.trans.shared.b16 {%0,%1,%2,%3}, [%4];"
        : "=r"(r[0]), "=r"(r[1]), "=r"(r[2]), "=r"(r[3]) : "r"(a));
}
__device__ __forceinline__ void mma_bf16(float* c, const uint32_t* a, const uint32_t* b) {
    asm volatile("mma.sync.aligned.m16n8k16.row.col.f32.bf16.bf16.f32 "
        "{%0,%1,%2,%3}, {%4,%5,%6,%7}, {%8,%9}, {%0,%1,%2,%3};"
        : "+f"(c[0]), "+f"(c[1]), "+f"(c[2]), "+f"(c[3])
        : "r"(a[0]), "r"(a[1]), "r"(a[2]), "r"(a[3]), "r"(b[0]), "r"(b[1]));
}
__device__ __forceinline__ void cp16(uint32_t dst, const void* src) {
    asm volatile("cp.async.cg.shared.global [%0], [%1], 16;" :: "r"(dst), "l"(src));
}
#define CP_COMMIT() asm volatile("cp.async.commit_group;" ::: "memory")
#define CP_WAIT2()  asm volatile("cp.async.wait_group 2;" ::: "memory")

// smem tile geometry: rows of 32 bf16 (64B) padded to 80B -> conflict-free LDSM
#define ROWB   80
#define STG_A  (128*ROWB)          // 10240
#define STG    (2*STG_A)           // 20480 per stage
#define NST    4
#define SMEM_REQ (NST*STG)         // 81920  (2 CTAs/SM)

// ---------------- misc device helpers ---------------------------------------
__device__ __forceinline__ float gelu_exact(float x) {
    return 0.5f * x * (1.0f + erff(x * 0.70710678118654752f));
}

// fast exp in the FMA pipe (no MUFU): exp(x) = 2^(x*log2e)
__device__ __forceinline__ float fexp(float x) {
    x = fmaxf(x, -60.0f);
    float y = x * 1.4426950408889634f;
    float t = y + 12582912.0f;            // 1.5 * 2^23
    float n = t - 12582912.0f;            // round(y)
    float r = y - n;                      // [-0.5, 0.5]
    float p = fmaf(0.0013333558f, r, 0.0096181298f);
    p = fmaf(p, r, 0.0555041087f);
    p = fmaf(p, r, 0.2402265070f);
    p = fmaf(p, r, 0.6931471806f);
    p = fmaf(p, r, 1.0f);
    int ni = (int)n;
    return p * __int_as_float((ni + 127) << 23);
}

// ---------------- bf16 GEMM (NT): C[M,N] = A[M,K]·W[N,K]^T + epilogue -------
// EPI: 1 bias(n)+gelu -> bf16    2 bias(n)+res -> f32
//      6 reproj fused: bias(m) + res(xnT flat) + res2(x flat) -> x1 (f32)
//      7 qkv: bias(n) -> bf16; A = (n0 < Cn) ? A : (bf16*)res
template<int EPI>
__global__ __launch_bounds__(256)
void gemm_bf16(const __nv_bfloat16* __restrict__ A, const __nv_bfloat16* __restrict__ W,
               const float* __restrict__ bias, const float* __restrict__ res,
               const float* __restrict__ res2,
               void* __restrict__ Cout, int Msz, int Nsz, int Ksz) {
    extern __shared__ char smem[];
    uint32_t sbase = smem_u32(smem);

    int tid = threadIdx.x;
    int wid = tid >> 5, lane = tid & 31;
    int m0 = blockIdx.y * 128, n0 = blockIdx.x * 128;
    int wm = (wid & 1) * 64, wn = (wid >> 1) * 32;
    int lrow = lane & 15;
    int lko  = (lane >> 4) * 16;

    const __nv_bfloat16* Aop = A;
    const __nv_bfloat16* Wop = W;
    const float* respZ = res;
    const float* res2Z = res2;
    float* CpF = (float*)Cout;
    __nv_bfloat16* CpH = (__nv_bfloat16*)Cout;
    if (EPI == 7) {
        if (n0 >= Cn) Aop = (const __nv_bfloat16*)res;   // k|v columns use vn
    }
    if (EPI == 6) {
        size_t z = blockIdx.z;
        size_t zoff = z * (size_t)Cn * Ln;
        Wop   = W + z * (size_t)Ln * Cn;
        respZ = res + zoff;
        res2Z = res2 + zoff;
        CpF   = (float*)Cout + zoff;
    }

    float acc[4][4][4];
    #pragma unroll
    for (int i = 0; i < 4; i++)
        #pragma unroll
        for (int j = 0; j < 4; j++)
            #pragma unroll
            for (int c = 0; c < 4; c++) acc[i][j][c] = 0.f;

    int arow = tid >> 2;
    int acol = tid & 3;

    auto load_chunk = [&](int kt, int s) {
        uint32_t dA = sbase + s * STG;
        uint32_t dB = dA + STG_A;
        const __nv_bfloat16* ga = Aop + (size_t)(m0 + arow) * Ksz + kt * 32 + acol * 8;
        cp16(dA + (uint32_t)(arow * ROWB + acol * 16), ga);
        cp16(dA + (uint32_t)((arow + 64) * ROWB + acol * 16), ga + (size_t)64 * Ksz);
        const __nv_bfloat16* gb = Wop + (size_t)(n0 + arow) * Ksz + kt * 32 + acol * 8;
        cp16(dB + (uint32_t)(arow * ROWB + acol * 16), gb);
        cp16(dB + (uint32_t)((arow + 64) * ROWB + acol * 16), gb + (size_t)64 * Ksz);
        CP_COMMIT();
    };

    int nk = Ksz >> 5;
    load_chunk(0, 0);
    load_chunk(1, 1);
    load_chunk(2, 2);

    for (int kt = 0; kt < nk; kt++) {
        int s = kt & 3;
        CP_WAIT2();
        __syncthreads();
        if (kt + 3 < nk) load_chunk(kt + 3, (kt + 3) & 3);
        else CP_COMMIT();

        uint32_t sA = sbase + s * STG;
        uint32_t sB = sA + STG_A;
        #pragma unroll
        for (int ks = 0; ks < 2; ks++) {
            uint32_t af[4][4], bf[2][4];
            #pragma unroll
            for (int mt = 0; mt < 4; mt++)
                ldsm4(af[mt], sA + (uint32_t)((wm + mt*16 + lrow) * ROWB + ks*32 + lko));
            #pragma unroll
            for (int g = 0; g < 2; g++)
                ldsm4(bf[g], sB + (uint32_t)((wn + g*16 + lrow) * ROWB + ks*32 + lko));
            #pragma unroll
            for (int mt = 0; mt < 4; mt++)
                #pragma unroll
                for (int nt = 0; nt < 4; nt++) {
                    uint32_t bb[2] = { bf[nt>>1][nt&1], bf[nt>>1][(nt&1) + 2] };
                    mma_bf16(acc[mt][nt], af[mt], bb);
                }
        }
    }

    int rm = lane >> 2, cn = (lane & 3) * 2;
    #pragma unroll
    for (int mt = 0; mt < 4; mt++) {
        int m = m0 + wm + mt*16 + rm;
        float bm0 = 0.f, bm1 = 0.f;
        if (EPI == 6) { bm0 = bias[m]; bm1 = bias[m + 8]; }
        #pragma unroll
        for (int nt = 0; nt < 4; nt++) {
            int n = n0 + wn + nt*8 + cn;
            float* c = acc[mt][nt];
            if (EPI == 1) {
                float2 bb = *(const float2*)&bias[n];
                __nv_bfloat162 p0 = __floats2bfloat162_rn(gelu_exact(c[0]+bb.x), gelu_exact(c[1]+bb.y));
                __nv_bfloat162 p1 = __floats2bfloat162_rn(gelu_exact(c[2]+bb.x), gelu_exact(c[3]+bb.y));
                *(__nv_bfloat162*)&CpH[(size_t)m * Nsz + n]     = p0;
                *(__nv_bfloat162*)&CpH[(size_t)(m+8) * Nsz + n] = p1;
            } else if (EPI == 2) {
                float2 bb = *(const float2*)&bias[n];
                float2 r0 = *(const float2*)&respZ[(size_t)m * Nsz + n];
                float2 r1 = *(const float2*)&respZ[(size_t)(m+8) * Nsz + n];
                *(float2*)&CpF[(size_t)m * Nsz + n]     = make_float2(c[0]+bb.x+r0.x, c[1]+bb.y+r0.y);
                *(float2*)&CpF[(size_t)(m+8) * Nsz + n] = make_float2(c[2]+bb.x+r1.x, c[3]+bb.y+r1.y);
            } else if (EPI == 7) {
                float2 bb = *(const float2*)&bias[n];
                __nv_bfloat162 p0 = __floats2bfloat162_rn(c[0]+bb.x, c[1]+bb.y);
                __nv_bfloat162 p1 = __floats2bfloat162_rn(c[2]+bb.x, c[3]+bb.y);
                *(__nv_bfloat162*)&CpH[(size_t)m * Nsz + n]     = p0;
                *(__nv_bfloat162*)&CpH[(size_t)(m+8) * Nsz + n] = p1;
            } else {  // EPI == 6
                size_t f0 = (size_t)m * Ln + n;
                size_t f1 = (size_t)(m+8) * Ln + n;
                float2 t0 = *(const float2*)&respZ[f0];
                float2 t1 = *(const float2*)&respZ[f1];
                float2 u0 = *(const float2*)&res2Z[f0];
                float2 u1 = *(const float2*)&res2Z[f1];
                *(float2*)&CpF[f0] = make_float2(c[0]+bm0+t0.x+u0.x, c[1]+bm0+t0.y+u0.y);
                *(float2*)&CpF[f1] = make_float2(c[2]+bm1+t1.x+u1.x, c[3]+bm1+t1.y+u1.y);
            }
        }
    }
}

// ---------------- fused front-end: LN1(x)+transpose | LN(v) | prep -----------
// Block ranges:
//   [0, 2304)       : LN1(x) + transpose (32 rows/block, needs LNX_SMEM)
//   [2304, 4608)    : LN(v) warp-per-row (32 rows/block)
//   [4608, 5442)    : prep (1024 units of 4 elems per block)
#define LNX_PITCH 513
#define LNX_SMEM  (32 * LNX_PITCH * 4)
#define PREP_UNITS 853376
#define NBLK_LN   (Mrows / 32)                 // 2304
#define NBLK_PREP ((PREP_UNITS + 1023) / 1024) // 834
#define NBLK_FUSED (2 * NBLK_LN + NBLK_PREP)   // 5442

__global__ __launch_bounds__(1024)
void front_kernel(const float* __restrict__ x, const float* __restrict__ ln1_w,
                  const float* __restrict__ ln1_b,
                  const float* __restrict__ v, const float* __restrict__ lnv_w,
                  const float* __restrict__ lnv_b,
                  __nv_bfloat16* __restrict__ xnb, float* __restrict__ xnT,
                  __nv_bfloat16* __restrict__ vnb,
                  const float* __restrict__ wq, const float* __restrict__ wk,
                  const float* __restrict__ wv, const float* __restrict__ wr,
                  const float* __restrict__ f1, const float* __restrict__ f2,
                  const float* __restrict__ bq, const float* __restrict__ bk,
                  const float* __restrict__ bv,
                  __nv_bfloat16* __restrict__ wqkvb,
                  __nv_bfloat16* __restrict__ wrb, __nv_bfloat16* __restrict__ f1b,
                  __nv_bfloat16* __restrict__ f2b, float* __restrict__ bqkv,
                  float* __restrict__ ctx, float* __restrict__ ksum) {
    extern __shared__ float s[];
    int bb = blockIdx.x;
    int tid = threadIdx.x;

    if (bb < NBLK_LN) {
        // ---- LN1(x) + transpose ----
        int wrp = tid >> 5, lane = tid & 31;
        int row0 = bb * 32;
        int row = row0 + wrp;
        size_t base = (size_t)row * Cn;

        float4 vv[4];
        float sum = 0.f;
        #pragma unroll
        for (int j = 0; j < 4; j++) {
            vv[j] = *(const float4*)(x + base + lane * 4 + j * 128);
            sum += vv[j].x + vv[j].y + vv[j].z + vv[j].w;
        }
        #pragma unroll
        for (int o = 16; o > 0; o >>= 1) sum += __shfl_xor_sync(0xffffffffu, sum, o);
        float mean = sum * (1.0f / Cn);
        float vs = 0.f;
        #pragma unroll
        for (int j = 0; j < 4; j++) {
            float d0 = vv[j].x - mean, d1 = vv[j].y - mean, d2 = vv[j].z - mean, d3 = vv[j].w - mean;
            vs += d0*d0 + d1*d1 + d2*d2 + d3*d3;
        }
        #pragma unroll
        for (int o = 16; o > 0; o >>= 1) vs += __shfl_xor_sync(0xffffffffu, vs, o);
        float rs = rsqrtf(vs * (1.0f / Cn) + 1e-5f);

        float* srow = s + wrp * LNX_PITCH;
        #pragma unroll
        for (int j = 0; j < 4; j++) {
            int c = lane * 4 + j * 128;
            float4 ww = *(const float4*)(ln1_w + c);
            float4 bbv = *(const float4*)(ln1_b + c);
            float o0 = (vv[j].x - mean) * rs * ww.x + bbv.x;
            float o1 = (vv[j].y - mean) * rs * ww.y + bbv.y;
            float o2 = (vv[j].z - mean) * rs * ww.z + bbv.z;
            float o3 = (vv[j].w - mean) * rs * ww.w + bbv.w;
            *(__nv_bfloat162*)(xnb + base + c)     = __floats2bfloat162_rn(o0, o1);
            *(__nv_bfloat162*)(xnb + base + c + 2) = __floats2bfloat162_rn(o2, o3);
            srow[c] = o0; srow[c+1] = o1; srow[c+2] = o2; srow[c+3] = o3;
        }
        __syncthreads();

        int bz = row0 / Ln;
        int lb = row0 - bz * Ln;
        float* op = xnT + (size_t)bz * Cn * Ln + lb;
        #pragma unroll
        for (int it = 0; it < 4; it++) {
            int idx = it * 1024 + tid;
            int c = idx >> 3, p = idx & 7;
            int l = p * 4;
            float4 ov = make_float4(s[(l+0) * LNX_PITCH + c], s[(l+1) * LNX_PITCH + c],
                                    s[(l+2) * LNX_PITCH + c], s[(l+3) * LNX_PITCH + c]);
            *(float4*)(op + (size_t)c * Ln + l) = ov;
        }
    } else if (bb < 2 * NBLK_LN) {
        // ---- LN(v) warp-per-row ----
        int wrp = tid >> 5, lane = tid & 31;
        int row = (bb - NBLK_LN) * 32 + wrp;
        size_t base = (size_t)row * Cn;

        float4 vv[4];
        float sum = 0.f;
        #pragma unroll
        for (int j = 0; j < 4; j++) {
            vv[j] = *(const float4*)(v + base + lane * 4 + j * 128);
            sum += vv[j].x + vv[j].y + vv[j].z + vv[j].w;
        }
        #pragma unroll
        for (int o = 16; o > 0; o >>= 1) sum += __shfl_xor_sync(0xffffffffu, sum, o);
        float mean = sum * (1.0f / Cn);
        float vs = 0.f;
        #pragma unroll
        for (int j = 0; j < 4; j++) {
            float d0 = vv[j].x - mean, d1 = vv[j].y - mean, d2 = vv[j].z - mean, d3 = vv[j].w - mean;
            vs += d0*d0 + d1*d1 + d2*d2 + d3*d3;
        }
        #pragma unroll
        for (int o = 16; o > 0; o >>= 1) vs += __shfl_xor_sync(0xffffffffu, vs, o);
        float rs = rsqrtf(vs * (1.0f / Cn) + 1e-5f);

        #pragma unroll
        for (int j = 0; j < 4; j++) {
            int c = lane * 4 + j * 128;
            float4 ww = *(const float4*)(lnv_w + c);
            float4 bbv = *(const float4*)(lnv_b + c);
            float o0 = (vv[j].x - mean) * rs * ww.x + bbv.x;
            float o1 = (vv[j].y - mean) * rs * ww.y + bbv.y;
            float o2 = (vv[j].z - mean) * rs * ww.z + bbv.z;
            float o3 = (vv[j].w - mean) * rs * ww.w + bbv.w;
            *(__nv_bfloat162*)(vnb + base + c)     = __floats2bfloat162_rn(o0, o1);
            *(__nv_bfloat162*)(vnb + base + c + 2) = __floats2bfloat162_rn(o2, o3);
        }
    } else {
        // ---- prep: weight cvt + bias concat + ctx/ksum zero ----
        int u = (bb - 2 * NBLK_LN) * 1024 + tid;
        const float* src;
        __nv_bfloat16* dst;
        int off;
        if (u < 65536)        { src = wq; dst = wqkvb; off = u; }
        else if (u < 131072)  { src = wk; dst = wqkvb + (size_t)Cn*Cn;   off = u - 65536; }
        else if (u < 196608)  { src = wv; dst = wqkvb + (size_t)2*Cn*Cn; off = u - 131072; }
        else if (u < 262144)  { src = wr; dst = wrb;  off = u - 196608; }
        else if (u < 524288)  { src = f1; dst = f1b;  off = u - 262144; }
        else if (u < 786432)  { src = f2; dst = f2b;  off = u - 524288; }
        else if (u < 786816)  {
            int i = (u - 786432) * 4;
            #pragma unroll
            for (int j = 0; j < 4; j++) {
                int k = i + j;
                bqkv[k] = (k < Cn) ? bq[k] : (k < 2*Cn ? bk[k - Cn] : bv[k - 2*Cn]);
            }
            return;
        } else if (u < 852352) {
            int i = (u - 786816) * 4;
            *(float4*)&ctx[i] = make_float4(0.f, 0.f, 0.f, 0.f);
            return;
        } else if (u < 853376) {
            int i = (u - 852352) * 4;
            *(float4*)&ksum[i] = make_float4(0.f, 0.f, 0.f, 0.f);
            return;
        } else return;
        int i = off * 4;
        float4 vv = *(const float4*)(src + i);
        *(__nv_bfloat162*)(dst + i)     = __floats2bfloat162_rn(vv.x, vv.y);
        *(__nv_bfloat162*)(dst + i + 2) = __floats2bfloat162_rn(vv.z, vv.w);
    }
}

// ---------------- warp-per-row LayerNorm (bf16 out, no block barriers) -------
__global__ __launch_bounds__(1024)
void ln_warp_kernel(const float* __restrict__ in, const float* __restrict__ w,
                    const float* __restrict__ b, __nv_bfloat16* __restrict__ outb) {
    int tid = threadIdx.x;
    int wrp = tid >> 5, lane = tid & 31;
    int row = blockIdx.x * 32 + wrp;
    size_t base = (size_t)row * Cn;

    float4 v[4];
    float sum = 0.f;
    #pragma unroll
    for (int j = 0; j < 4; j++) {
        v[j] = *(const float4*)(in + base + lane * 4 + j * 128);
        sum += v[j].x + v[j].y + v[j].z + v[j].w;
    }
    #pragma unroll
    for (int o = 16; o > 0; o >>= 1) sum += __shfl_xor_sync(0xffffffffu, sum, o);
    float mean = sum * (1.0f / Cn);
    float vs = 0.f;
    #pragma unroll
    for (int j = 0; j < 4; j++) {
        float d0 = v[j].x - mean, d1 = v[j].y - mean, d2 = v[j].z - mean, d3 = v[j].w - mean;
        vs += d0*d0 + d1*d1 + d2*d2 + d3*d3;
    }
    #pragma unroll
    for (int o = 16; o > 0; o >>= 1) vs += __shfl_xor_sync(0xffffffffu, vs, o);
    float rs = rsqrtf(vs * (1.0f / Cn) + 1e-5f);

    #pragma unroll
    for (int j = 0; j < 4; j++) {
        int c = lane * 4 + j * 128;
        float4 ww = *(const float4*)(w + c);
        float4 bb = *(const float4*)(b + c);
        float o0 = (v[j].x - mean) * rs * ww.x + bb.x;
        float o1 = (v[j].y - mean) * rs * ww.y + bb.y;
        float o2 = (v[j].z - mean) * rs * ww.z + bb.z;
        float o3 = (v[j].w - mean) * rs * ww.w + bb.w;
        *(__nv_bfloat162*)(outb + base + c)     = __floats2bfloat162_rn(o0, o1);
        *(__nv_bfloat162*)(outb + base + c + 2) = __floats2bfloat162_rn(o2, o3);
    }
}

// ------- context (tensorized): ctx[64kk,64vv] += EK^T · V over l -------------
#define CSTR 72
__global__ __launch_bounds__(256)
void context_kernel(const __nv_bfloat16* __restrict__ qkvb,
                    float* __restrict__ ctx, float* __restrict__ ksum) {
    __shared__ __nv_bfloat16 sEK[64*CSTR];
    __shared__ __nv_bfloat16 sV [64*CSTR];
    __shared__ float red[64];
    int b = blockIdx.z, h = blockIdx.y;
    int l0 = blockIdx.x * (Ln / 16);          // 576 l per block, 9 chunks of 64
    int tid = threadIdx.x;
    int wid = tid >> 5, lane = tid & 31;
    int r0 = tid >> 3;            // 0..31 (l row)
    int sg = tid & 7;             // 8-channel segment
    if (tid < 64) red[tid] = 0.f;

    int wm = (wid & 3) * 16;      // kk chunk
    int wn = (wid >> 2) * 32;     // vv chunk
    int tr = (lane & 7) + ((lane >> 4) << 3);
    int tc = ((lane >> 3) & 1) * 8;

    uint32_t ekb = smem_u32(sEK);
    uint32_t vb  = smem_u32(sV);

    float ps[8] = {};
    float acc[4][4] = {};

    for (int c = 0; c < 9; c++) {
        int lc = l0 + c * 64;
        #pragma unroll
        for (int rr = 0; rr < 2; rr++) {
            int r = r0 + rr * 32;
            const __nv_bfloat16* gk = qkvb + ((size_t)(b * Ln + lc + r)) * QKV + Cn + h * DK + sg * 8;
            uint4 kraw = *(const uint4*)gk;
            uint4 vraw = *(const uint4*)(gk + Cn);
            __nv_bfloat16 tmp[8], eo[8];
            *(uint4*)tmp = kraw;
            #pragma unroll
            for (int j = 0; j < 8; j++) {
                float e = fexp(__bfloat162float(tmp[j]));
                ps[j] += e;
                eo[j] = __float2bfloat16_rn(e);
            }
            *(uint4*)&sEK[r * CSTR + sg * 8] = *(uint4*)eo;
            *(uint4*)&sV [r * CSTR + sg * 8] = vraw;
        }
        __syncthreads();
        #pragma unroll
        for (int ks = 0; ks < 4; ks++) {
            uint32_t af[4], bf[2][4];
            uint32_t rowoff = (uint32_t)((ks * 16 + tr) * CSTR * 2);
            ldsm4t(af,    ekb + rowoff + (uint32_t)((wm + tc) * 2));
            ldsm4t(bf[0], vb  + rowoff + (uint32_t)((wn + tc) * 2));
            ldsm4t(bf[1], vb  + rowoff + (uint32_t)((wn + 16 + tc) * 2));
            #pragma unroll
            for (int nt = 0; nt < 4; nt++) {
                uint32_t bb[2] = { bf[nt>>1][nt&1], bf[nt>>1][(nt&1) + 2] };
                mma_bf16(acc[nt], af, bb);
            }
        }
        __syncthreads();
    }

    #pragma unroll
    for (int j = 0; j < 8; j++) atomicAdd(&red[sg * 8 + j], ps[j]);
    __syncthreads();
    if (tid < 64) atomicAdd(&ksum[b * Cn + h * DK + tid], red[tid]);

    int rm = lane >> 2, cnq = (lane & 3) * 2;
    size_t cb = (size_t)(b * Hn + h) * DK * DK;
    #pragma unroll
    for (int nt = 0; nt < 4; nt++) {
        int n = wn + nt * 8 + cnq;
        float* cc = acc[nt];
        atomicAdd(&ctx[cb + (size_t)(wm + rm) * DK + n],       cc[0]);
        atomicAdd(&ctx[cb + (size_t)(wm + rm) * DK + n + 1],   cc[1]);
        atomicAdd(&ctx[cb + (size_t)(wm + rm + 8) * DK + n],   cc[2]);
        atomicAdd(&ctx[cb + (size_t)(wm + rm + 8) * DK + n+1], cc[3]);
    }
}

// ---- agg (tensorized): aggT[l, ch] = P[l,kk] · ctxn^T[kk,vv] ----------------
__global__ __launch_bounds__(256)
void agg_kernel(const __nv_bfloat16* __restrict__ qkvb, const float* __restrict__ ctx,
                const float* __restrict__ ksum, __nv_bfloat16* __restrict__ aggT) {
    __shared__ __nv_bfloat16 sP [128*CSTR];   // [l][kk]
    __shared__ __nv_bfloat16 sCt[64*CSTR];    // [vv][kk]
    __shared__ float sZ[64];
    int b = blockIdx.z, h = blockIdx.y, l0 = blockIdx.x * 128;
    int tid = threadIdx.x;
    int wid = tid >> 5, lane = tid & 31;

    if (tid < 64) sZ[tid] = 1.0f / ksum[b * Cn + h * DK + tid];
    __syncthreads();

    size_t cb = (size_t)(b * Hn + h) * DK * DK;
    for (int f = tid; f < 4096; f += 256) {
        int kk = f >> 6, vv = f & 63;
        sCt[vv * CSTR + kk] = __float2bfloat16_rn(ctx[cb + f] * sZ[kk]);
    }

    {
        int r = tid >> 1;
        int off = (tid & 1) * 32;
        const __nv_bfloat16* gq = qkvb + ((size_t)(b * Ln + l0 + r)) * QKV + h * DK + off;
        __nv_bfloat16 qv[32];
        *(uint4*)&qv[0]  = *(const uint4*)(gq);
        *(uint4*)&qv[8]  = *(const uint4*)(gq + 8);
        *(uint4*)&qv[16] = *(const uint4*)(gq + 16);
        *(uint4*)&qv[24] = *(const uint4*)(gq + 24);
        float e[32];
        float s = 0.f;
        #pragma unroll
        for (int j = 0; j < 32; j++) {
            e[j] = fexp(__bfloat162float(qv[j]));
            s += e[j];
        }
        s += __shfl_xor_sync(0xffffffffu, s, 1);
        float inv = 1.0f / s;
        __nv_bfloat16* pp = &sP[r * CSTR + off];
        #pragma unroll
        for (int j = 0; j < 32; j += 2)
            *(__nv_bfloat162*)(pp + j) = __floats2bfloat162_rn(e[j] * inv, e[j+1] * inv);
    }
    __syncthreads();

    int wm = (wid & 3) * 32, wn = (wid >> 2) * 32;
    int lrow = lane & 15, lko = (lane >> 4) * 16;
    uint32_t pb = smem_u32(sP), ctb = smem_u32(sCt);
    float acc[2][4][4] = {};
    #pragma unroll
    for (int ks = 0; ks < 4; ks++) {     // 4 k16 steps over kk
        uint32_t koff = (uint32_t)(ks * 32 + lko);
        uint32_t af[2][4], bf[2][4];
        #pragma unroll
        for (int mt = 0; mt < 2; mt++)
            ldsm4(af[mt], pb + (uint32_t)((wm + mt*16 + lrow) * CSTR * 2) + koff);
        #pragma unroll
        for (int g = 0; g < 2; g++)
            ldsm4(bf[g], ctb + (uint32_t)((wn + g*16 + lrow) * CSTR * 2) + koff);
        #pragma unroll
        for (int mt = 0; mt < 2; mt++)
            #pragma unroll
            for (int nt = 0; nt < 4; nt++) {
                uint32_t bb[2] = { bf[nt>>1][nt&1], bf[nt>>1][(nt&1) + 2] };
                mma_bf16(acc[mt][nt], af[mt], bb);
            }
    }

    int rm = lane >> 2, cnq = (lane & 3) * 2;
    #pragma unroll
    for (int mt = 0; mt < 2; mt++) {
        int l = wm + mt * 16 + rm;
        size_t ob0 = ((size_t)(b * Ln + l0 + l)) * Cn + h * DK;
        size_t ob1 = ((size_t)(b * Ln + l0 + l + 8)) * Cn + h * DK;
        #pragma unroll
        for (int nt = 0; nt < 4; nt++) {
            int n = wn + nt * 8 + cnq;
            float* cc = acc[mt][nt];
            *(__nv_bfloat162*)&aggT[ob0 + n] = __floats2bfloat162_rn(cc[0], cc[1]);
            *(__nv_bfloat162*)&aggT[ob1 + n] = __floats2bfloat162_rn(cc[2], cc[3]);
        }
    }
}

// ---------------- host launcher ---------------------------------------------
extern "C" void kernel_launch(void* const* d_in, const int* in_sizes, int n_in,
                              void* d_out, int out_size) {
    (void)in_sizes; (void)n_in; (void)out_size;
    const float* x     = (const float*)d_in[0];
    const float* v     = (const float*)d_in[1];
    const float* ln1_w = (const float*)d_in[4];
    const float* ln1_b = (const float*)d_in[5];
    const float* lnv_w = (const float*)d_in[6];
    const float* lnv_b = (const float*)d_in[7];
    const float* ln2_w = (const float*)d_in[8];
    const float* ln2_b = (const float*)d_in[9];
    const float* wq    = (const float*)d_in[10];
    const float* bq    = (const float*)d_in[11];
    const float* wk    = (const float*)d_in[12];
    const float* bk    = (const float*)d_in[13];
    const float* wv    = (const float*)d_in[14];
    const float* bv    = (const float*)d_in[15];
    const float* wr    = (const float*)d_in[16];
    const float* br    = (const float*)d_in[17];
    const float* fc1_w = (const float*)d_in[18];
    const float* fc1_b = (const float*)d_in[19];
    const float* fc2_w = (const float*)d_in[20];
    const float* fc2_b = (const float*)d_in[21];
    float* out = (float*)d_out;

    float *p_xnT, *p_ksum, *p_ctx, *p_x1, *p_bqkv;
    __nv_bfloat16 *p_xnb, *p_vnb, *p_qkvb, *p_aggT, *p_x1nb, *p_h1b;
    __nv_bfloat16 *p_wqkvb, *p_wrb, *p_f1b, *p_f2b;
    cudaGetSymbolAddress((void**)&p_xnT, g_xnT);
    cudaGetSymbolAddress((void**)&p_xnb, g_xnb);
    cudaGetSymbolAddress((void**)&p_vnb, g_vnb);
    cudaGetSymbolAddress((void**)&p_qkvb,g_qkvb);
    cudaGetSymbolAddress((void**)&p_ksum,g_ksum);
    cudaGetSymbolAddress((void**)&p_ctx, g_ctx);
    cudaGetSymbolAddress((void**)&p_aggT,g_aggT);
    cudaGetSymbolAddress((void**)&p_x1,  g_x1);
    cudaGetSymbolAddress((void**)&p_x1nb,g_x1nb);
    cudaGetSymbolAddress((void**)&p_h1b, g_h1b);
    cudaGetSymbolAddress((void**)&p_wqkvb,g_wqkvb);
    cudaGetSymbolAddress((void**)&p_wrb, g_wrb);
    cudaGetSymbolAddress((void**)&p_f1b, g_f1b);
    cudaGetSymbolAddress((void**)&p_f2b, g_f2b);
    cudaGetSymbolAddress((void**)&p_bqkv,g_bqkv);

    cudaFuncSetAttribute(gemm_bf16<1>, cudaFuncAttributeMaxDynamicSharedMemorySize, SMEM_REQ);
    cudaFuncSetAttribute(gemm_bf16<2>, cudaFuncAttributeMaxDynamicSharedMemorySize, SMEM_REQ);
    cudaFuncSetAttribute(gemm_bf16<6>, cudaFuncAttributeMaxDynamicSharedMemorySize, SMEM_REQ);
    cudaFuncSetAttribute(gemm_bf16<7>, cudaFuncAttributeMaxDynamicSharedMemorySize, SMEM_REQ);
    cudaFuncSetAttribute(front_kernel, cudaFuncAttributeMaxDynamicSharedMemorySize, LNX_SMEM);

    // 0) fused front-end: LN1(x)+transpose | LN(v) | prep (one launch)
    front_kernel<<<NBLK_FUSED, 1024, LNX_SMEM>>>(
        x, ln1_w, ln1_b, v, lnv_w, lnv_b, p_xnb, p_xnT, p_vnb,
        wq, wk, wv, wr, fc1_w, fc2_w, bq, bk, bv,
        p_wqkvb, p_wrb, p_f1b, p_f2b, p_bqkv, p_ctx, p_ksum);

    // 1) fused q|k|v projection (N=1536; A chosen per n-block)
    gemm_bf16<7><<<dim3(QKV / 128, Mrows / 128), 256, SMEM_REQ>>>(
        p_xnb, p_wqkvb, p_bqkv, (const float*)p_vnb, nullptr, p_qkvb, Mrows, QKV, Cn);

    // 2) context = sum_l exp(k)·val (unnormalized, tensorized) + ksum
    context_kernel<<<dim3(16, Hn, Bn), 256>>>(p_qkvb, p_ctx, p_ksum);

    // 3) aggT = softmax(q) @ (ctx/ksum)  -> (B, L, C) bf16 (tensorized)
    agg_kernel<<<dim3(Ln / 128, Hn, Bn), 256>>>(p_qkvb, p_ctx, p_ksum, p_aggT);

    // 4) reproj fused: x1 = wr·aggT + br + xnT + x
    gemm_bf16<6><<<dim3(Ln / 128, Cn / 128, Bn), 256, SMEM_REQ>>>(
        p_wrb, p_aggT, br, p_xnT, x, p_x1, Cn, Ln, Cn);

    // 5) x1n = LN(x1) (bf16, warp-per-row)
    ln_warp_kernel<<<Mrows / 32, 1024>>>(p_x1, ln2_w, ln2_b, p_x1nb);

    // 6) MLP
    gemm_bf16<1><<<dim3(HID / 128, Mrows / 128), 256, SMEM_REQ>>>(
        p_x1nb, p_f1b, fc1_b, nullptr, nullptr, p_h1b, Mrows, HID, Cn);
    gemm_bf16<2><<<dim3(Cn / 128, Mrows / 128), 256, SMEM_REQ>>>(
        p_h1b, p_f2b, fc2_b, p_x1, nullptr, out, Mrows, Cn, HID);
}